// round 4
// baseline (speedup 1.0000x reference)
#include <cuda_runtime.h>
#include <math.h>
#include <stdint.h>

#define BB 4
#define TT 1024
#define DD 1024
#define HH 16
#define DKV 64
#define FFD 4096

// ---------------- scratch (device globals; no allocation allowed) ----------------
__device__ float g_Wt0[DD * DD];
__device__ float g_Wt1[DD * DD];
__device__ float g_Wt2[DD * DD];
__device__ float g_WoT[DD * DD];
__device__ float g_Q  [BB * TT * DD];
__device__ float g_K  [BB * TT * DD];
__device__ float g_V  [BB * TT * DD];
__device__ float g_Vt [BB * HH * DKV * TT];
__device__ float g_S  [(size_t)BB * HH * TT * TT];   // 256 MB
__device__ float g_dinv[BB * HH * TT];
__device__ float g_P  [BB * TT * DD];
__device__ float g_M  [BB * TT * DD];
__device__ float g_o1 [BB * TT * DD];
__device__ float g_o2 [BB * TT * DD];
__device__ float g_hid[(size_t)BB * TT * FFD];       // 64 MB
__device__ float g_ff [BB * TT * DD];

// ---------------- helpers ----------------
__device__ __forceinline__ uint32_t smem_u32(const void* p) {
    uint32_t a;
    asm("{ .reg .u64 t; cvta.to.shared.u64 t, %1; cvt.u32.u64 %0, t; }" : "=r"(a) : "l"(p));
    return a;
}
// exact split: v = hi + lo, hi has 10 mantissa bits (tf32-exact).
// lo is consumed by HMMA's HW fp32->tf32 truncation (error ~2^-21 rel).
__device__ __forceinline__ void split2(float v, uint32_t& hi, uint32_t& lo) {
    uint32_t h = __float_as_uint(v) & 0xffffe000u;
    hi = h;
    lo = __float_as_uint(v - __uint_as_float(h));
}
__device__ __forceinline__ void mma_tf32(float* c, const uint32_t* a, const uint32_t* b) {
    asm volatile(
        "mma.sync.aligned.m16n8k8.row.col.f32.tf32.tf32.f32 "
        "{%0,%1,%2,%3}, {%4,%5,%6,%7}, {%8,%9}, {%0,%1,%2,%3};"
        : "+f"(c[0]), "+f"(c[1]), "+f"(c[2]), "+f"(c[3])
        : "r"(a[0]), "r"(a[1]), "r"(a[2]), "r"(a[3]), "r"(b[0]), "r"(b[1]));
}

// ---------------- tf32 mma.sync GEMM: C[M,N] = alpha * A[M,K] @ B[N,K]^T ----------
// A K-major (lda), B K-major (ldb). 3xTF32 split (fp32-grade accuracy).
// BM=128, BN=64, BK=32, NST=2 cp.async pipeline, 3 CTAs/SM target.
// k-columns are logically permuted (identically for A and B) so each thread's
// per-MMA fragment pair is a contiguous float2 in shared memory.
template<bool BIAS_, bool RELU_, bool EXP_>
__global__ __launch_bounds__(256, 3)
void mma_gemm(const float* __restrict__ A, const float* __restrict__ B,
              const float* __restrict__ bias, float* __restrict__ C,
              int K, int lda, int ldb, int ldc,
              long sA1, long sA2, long sB1, long sB2, long sC1, long sC2,
              int zdiv, float alpha)
{
    constexpr int BM = 128, BN = 64, BK = 32, NST = 2;
    constexpr int WN = BN / 2;         // 32 (warps: 4 x 2)
    constexpr int NT = WN / 8;         // 4
    constexpr int MT = 2;              // 32 rows per warp
    constexpr int RS = 36;             // smem row stride (floats); 144B, 16B-aligned
    constexpr int STG = (BM + BN) * RS;
    constexpr int NLD = (BM + BN) * 8; // float4 loads per stage

    extern __shared__ float sm[];
    const uint32_t smb = smem_u32(sm);

    const int tid  = threadIdx.x;
    const int lane = tid & 31;
    const int wid  = tid >> 5;
    const int wm   = wid >> 1;         // 0..3
    const int wn   = wid & 1;          // 0..1

    const int z  = blockIdx.z;
    const int z1 = z / zdiv, z2 = z % zdiv;
    A += z1 * sA1 + z2 * sA2;
    B += z1 * sB1 + z2 * sB2;
    C += z1 * sC1 + z2 * sC2;

    const int row0 = blockIdx.y * BM;
    const int col0 = blockIdx.x * BN;

    float acc[MT][NT][4];
    #pragma unroll
    for (int i = 0; i < MT; i++)
        #pragma unroll
        for (int j = 0; j < NT; j++)
            #pragma unroll
            for (int q = 0; q < 4; q++) acc[i][j][q] = 0.f;

    const int nch = K / BK;

    auto copy_stage = [&](int s, int c) {
        const int kk = c * BK;
        #pragma unroll
        for (int i = tid; i < NLD; i += 256) {
            const bool isA = (i < BM * 8);
            const int j = isA ? i : (i - BM * 8);
            const int r = j >> 3, c4 = j & 7;
            const float* gp = isA ? (A + (long)(row0 + r) * lda + kk + c4 * 4)
                                  : (B + (long)(col0 + r) * ldb + kk + c4 * 4);
            uint32_t dst = smb + 4u * (uint32_t)(s * STG + (isA ? 0 : BM * RS) + r * RS + c4 * 4);
            asm volatile("cp.async.cg.shared.global [%0], [%1], 16;" :: "r"(dst), "l"(gp));
        }
    };

    // prologue: stage 0
    copy_stage(0, 0);
    asm volatile("cp.async.commit_group;" ::: "memory");

    const int ar = wm * 32 + (lane >> 2);      // A row within CTA tile
    const int ac = lane & 3;                   // k sub-lane
    const int br = wn * WN + (lane >> 2);      // B row within CTA tile
    const int kperm = ac * 8;                  // permuted k base: logical ac+4m -> global ac*8+m

    for (int c = 0; c < nch; c++) {
        if (c + 1 < nch) copy_stage((c + 1) & 1, c + 1);
        asm volatile("cp.async.commit_group;" ::: "memory");
        asm volatile("cp.async.wait_group 1;" ::: "memory");
        __syncthreads();

        const float* As = sm + (c & 1) * STG;
        const float* Bs = As + BM * RS;

        #pragma unroll
        for (int ks = 0; ks < 4; ks++) {
            // per-thread fragment elements for MMA ks are the contiguous float2
            // at permuted columns (ac*8 + 2ks, +1): .x -> k0, .y -> k0+4
            uint32_t Ahi[MT][4], Alo[MT][4];
            #pragma unroll
            for (int mt = 0; mt < MT; mt++) {
                const float* ap = As + (ar + mt * 16) * RS + kperm + 2 * ks;
                float2 v0 = *(const float2*)ap;
                float2 v1 = *(const float2*)(ap + 8 * RS);
                split2(v0.x, Ahi[mt][0], Alo[mt][0]);
                split2(v1.x, Ahi[mt][1], Alo[mt][1]);
                split2(v0.y, Ahi[mt][2], Alo[mt][2]);
                split2(v1.y, Ahi[mt][3], Alo[mt][3]);
            }
            uint32_t Bhi[NT][2], Blo[NT][2];
            #pragma unroll
            for (int nt = 0; nt < NT; nt++) {
                float2 bv = *(const float2*)(Bs + (br + nt * 8) * RS + kperm + 2 * ks);
                split2(bv.x, Bhi[nt][0], Blo[nt][0]);
                split2(bv.y, Bhi[nt][1], Blo[nt][1]);
            }
            #pragma unroll
            for (int mt = 0; mt < MT; mt++)
                #pragma unroll
                for (int nt = 0; nt < NT; nt++) {
                    mma_tf32(acc[mt][nt], Ahi[mt], Bhi[nt]);
                    mma_tf32(acc[mt][nt], Ahi[mt], Blo[nt]);
                    mma_tf32(acc[mt][nt], Alo[mt], Bhi[nt]);
                }
        }
        __syncthreads();
    }

    // epilogue
    const int rbase = row0 + wm * 32 + (lane >> 2);
    const int cbase = col0 + wn * WN + (lane & 3) * 2;
    #pragma unroll
    for (int mt = 0; mt < MT; mt++) {
        #pragma unroll
        for (int half = 0; half < 2; half++) {
            const long gm = rbase + mt * 16 + half * 8;
            float* crow = C + gm * ldc;
            #pragma unroll
            for (int nt = 0; nt < NT; nt++) {
                const int gn = cbase + nt * 8;
                float v0 = acc[mt][nt][half * 2 + 0] * alpha;
                float v1 = acc[mt][nt][half * 2 + 1] * alpha;
                if (EXP_)  { v0 = __expf(v0); v1 = __expf(v1); }
                if (BIAS_) { v0 += bias[gn]; v1 += bias[gn + 1]; }
                if (RELU_) { v0 = fmaxf(v0, 0.f); v1 = fmaxf(v1, 0.f); }
                float2 o; o.x = v0; o.y = v1;
                *(float2*)(crow + gn) = o;
            }
        }
    }
}

// ---------------- tiled transpose: out[z][c][r] = in[z][r][c] (* scale[z][r]) -----
template<bool SC>
__global__ void transpose_k(const float* __restrict__ in, float* __restrict__ out,
                            const float* __restrict__ scale,
                            int R, int C, int ldin, int ldout,
                            long inS1, long inS2, int zdiv)
{
    __shared__ float tile[32][33];
    const int z = blockIdx.z;
    in  += (long)(z / zdiv) * inS1 + (long)(z % zdiv) * inS2;
    out += (long)z * (long)C * ldout;
    if (SC) scale += (long)z * R;
    const int c0 = blockIdx.x * 32, r0 = blockIdx.y * 32;
    const int tx = threadIdx.x, ty = threadIdx.y;
    #pragma unroll
    for (int i = ty; i < 32; i += 8) {
        float v = in[(long)(r0 + i) * ldin + c0 + tx];
        if (SC) v *= scale[r0 + i];
        tile[i][tx] = v;
    }
    __syncthreads();
    #pragma unroll
    for (int i = ty; i < 32; i += 8)
        out[(long)(c0 + i) * ldout + r0 + tx] = tile[tx][i];
}

// -------- deterministic per-column (query-axis) softmax denominator --------------
__global__ void colsum_inv(const float* __restrict__ S, float* __restrict__ dinv) {
    const int z = blockIdx.y;
    const int s = blockIdx.x * 256 + threadIdx.x;
    const float* p = S + (long)z * 1048576 + s;
    float acc = 0.f;
    #pragma unroll 8
    for (int t = 0; t < 1024; t++) acc += p[(long)t * 1024];
    dinv[z * 1024 + s] = 1.f / acc;
}

// ---------------- reductions + sub_norm -------------------------------------------
__device__ __forceinline__ float blockReduceSum(float v) {
    __shared__ float sh[32];
    __syncthreads();
    int lane = threadIdx.x & 31, wid = threadIdx.x >> 5;
    #pragma unroll
    for (int o = 16; o; o >>= 1) v += __shfl_xor_sync(0xffffffffu, v, o);
    if (lane == 0) sh[wid] = v;
    __syncthreads();
    if (wid == 0) {
        v = (threadIdx.x < (blockDim.x >> 5)) ? sh[lane] : 0.f;
        #pragma unroll
        for (int o = 16; o; o >>= 1) v += __shfl_xor_sync(0xffffffffu, v, o);
        if (lane == 0) sh[0] = v;
    }
    __syncthreads();
    return sh[0];
}

__global__ void add_subnorm(const float* __restrict__ A, const float* __restrict__ R,
                            float* __restrict__ O) {
    long base = (long)blockIdx.x * 1024;
    int t = threadIdx.x;
    float v[4];
    float s = 0.f;
    #pragma unroll
    for (int j = 0; j < 4; j++) { v[j] = A[base + t + j * 256] + R[base + t + j * 256]; s += v[j]; }
    s = blockReduceSum(s);
    float mean = s * (1.f / 1024.f);
    float q = 0.f;
    #pragma unroll
    for (int j = 0; j < 4; j++) { float d = v[j] - mean; q += d * d; }
    q = blockReduceSum(q);
    float sd = sqrtf(q * (1.f / 1023.f));
    #pragma unroll
    for (int j = 0; j < 4; j++) O[base + t + j * 256] = v[j] - mean - sd;
}

// ---------------- host --------------------------------------------------------------
static const int SMB = 2 * (128 + 64) * 36 * 4;   // 55,296 B -> 3+ CTAs/SM

extern "C" void kernel_launch(void* const* d_in, const int* in_sizes, int n_in,
                              void* d_out, int out_size) {
    const float* x    = (const float*)d_in[0];
    const float* y    = (const float*)d_in[1];
    const float* Wq1  = (const float*)d_in[2];
    const float* Wk1  = (const float*)d_in[3];
    const float* Wv1  = (const float*)d_in[4];
    const float* Wo1  = (const float*)d_in[5];
    const float* Wq2  = (const float*)d_in[6];
    const float* Wk2  = (const float*)d_in[7];
    const float* Wv2  = (const float*)d_in[8];
    const float* Wo2  = (const float*)d_in[9];
    const float* W_in = (const float*)d_in[10];
    const float* b_in = (const float*)d_in[11];
    const float* W_out= (const float*)d_in[12];
    const float* b_out= (const float*)d_in[13];
    float* out = (float*)d_out;

    float *Wt0, *Wt1, *Wt2, *WoT, *Q, *K, *V, *Vt, *S, *dinv, *P, *M, *o1, *o2, *hid, *ff;
    cudaGetSymbolAddress((void**)&Wt0, g_Wt0);
    cudaGetSymbolAddress((void**)&Wt1, g_Wt1);
    cudaGetSymbolAddress((void**)&Wt2, g_Wt2);
    cudaGetSymbolAddress((void**)&WoT, g_WoT);
    cudaGetSymbolAddress((void**)&Q,   g_Q);
    cudaGetSymbolAddress((void**)&K,   g_K);
    cudaGetSymbolAddress((void**)&V,   g_V);
    cudaGetSymbolAddress((void**)&Vt,  g_Vt);
    cudaGetSymbolAddress((void**)&S,   g_S);
    cudaGetSymbolAddress((void**)&dinv,g_dinv);
    cudaGetSymbolAddress((void**)&P,   g_P);
    cudaGetSymbolAddress((void**)&M,   g_M);
    cudaGetSymbolAddress((void**)&o1,  g_o1);
    cudaGetSymbolAddress((void**)&o2,  g_o2);
    cudaGetSymbolAddress((void**)&hid, g_hid);
    cudaGetSymbolAddress((void**)&ff,  g_ff);

    cudaFuncSetAttribute(mma_gemm<false,false,false>, cudaFuncAttributeMaxDynamicSharedMemorySize, SMB);
    cudaFuncSetAttribute(mma_gemm<false,false,true >, cudaFuncAttributeMaxDynamicSharedMemorySize, SMB);
    cudaFuncSetAttribute(mma_gemm<true ,true ,false>, cudaFuncAttributeMaxDynamicSharedMemorySize, SMB);
    cudaFuncSetAttribute(mma_gemm<true ,false,false>, cudaFuncAttributeMaxDynamicSharedMemorySize, SMB);

    dim3 blkT(32, 8);
    const long Z0 = 0;

    auto run_mha = [&](const float* qsrc, const float* kvsrc,
                       const float* Wq, const float* Wk, const float* Wv, const float* Wo,
                       const float* resid, float* obuf) {
        // repack per-head weights (H,D,dk) -> [(h,k), d]
        dim3 gw(2, 32, HH);
        transpose_k<false><<<gw, blkT>>>(Wq, Wt0, nullptr, 1024, 64, 64, 1024, 65536, 0, 1);
        transpose_k<false><<<gw, blkT>>>(Wk, Wt1, nullptr, 1024, 64, 64, 1024, 65536, 0, 1);
        transpose_k<false><<<gw, blkT>>>(Wv, Wt2, nullptr, 1024, 64, 64, 1024, 65536, 0, 1);

        // projections: (4096,1024) x (1024,1024)^T
        dim3 gp(16, 32, 1);
        mma_gemm<false,false,false><<<gp, 256, SMB>>>(
            qsrc, Wt0, nullptr, Q, 1024, 1024, 1024, 1024, Z0,Z0,Z0,Z0,Z0,Z0, 1, 1.f);
        mma_gemm<false,false,false><<<gp, 256, SMB>>>(
            kvsrc, Wt1, nullptr, K, 1024, 1024, 1024, 1024, Z0,Z0,Z0,Z0,Z0,Z0, 1, 1.f);
        mma_gemm<false,false,false><<<gp, 256, SMB>>>(
            kvsrc, Wt2, nullptr, V, 1024, 1024, 1024, 1024, Z0,Z0,Z0,Z0,Z0,Z0, 1, 1.f);

        // scores: S[(b,h), t, s] = exp( Q.K^T / 8 )
        dim3 gs(16, 8, BB * HH);
        mma_gemm<false,false,true><<<gs, 256, SMB>>>(
            Q, K, nullptr, S, 64, 1024, 1024, 1024,
            1048576, 64, 1048576, 64, 16777216, 1048576, HH, 0.125f);

        // softmax denominator over query axis t (deterministic column sums)
        colsum_inv<<<dim3(4, BB * HH), 256>>>(S, dinv);

        // V transpose + fold dinv: Vt[(b,h), v, s] = V[b, s, (h,v)] * dinv[(b,h), s]
        dim3 gv(2, 32, BB * HH);
        transpose_k<true><<<gv, blkT>>>(V, Vt, dinv, 1024, 64, 1024, 1024, 1048576, 64, HH);

        // partial: P[b, t, (h,v)] = sum_s expS[t,s] * Vt'[v,s]
        dim3 gpp(1, 8, BB * HH);
        mma_gemm<false,false,false><<<gpp, 256, SMB>>>(
            S, Vt, nullptr, P, 1024, 1024, 1024, 1024,
            16777216, 1048576, 1048576, 65536, 1048576, 64, HH, 1.f);

        // output projection
        dim3 gwo(32, 32, 1);
        transpose_k<false><<<gwo, blkT>>>(Wo, WoT, nullptr, 1024, 1024, 1024, 1024, Z0, Z0, 1);
        mma_gemm<false,false,false><<<gp, 256, SMB>>>(
            P, WoT, nullptr, M, 1024, 1024, 1024, 1024, Z0,Z0,Z0,Z0,Z0,Z0, 1, 1.f);

        add_subnorm<<<BB * TT, 256>>>(M, resid, obuf);
    };

    // out1 = sub_norm(mha(y,y,y) + y)
    run_mha(y, y, Wq1, Wk1, Wv1, Wo1, y, o1);
    // out2 = sub_norm(mha(y,x,x) + out1)
    run_mha(y, x, Wq2, Wk2, Wv2, Wo2, o1, o2);

    // FFN on y: hid = relu(y @ W_in^T + b_in); ff = hid @ W_out^T + b_out
    dim3 gf1(64, 32, 1);
    mma_gemm<true,true,false><<<gf1, 256, SMB>>>(
        y, W_in, b_in, hid, 1024, 1024, 1024, 4096, Z0,Z0,Z0,Z0,Z0,Z0, 1, 1.f);
    dim3 gf2(16, 32, 1);
    mma_gemm<true,false,false><<<gf2, 256, SMB>>>(
        hid, W_out, b_out, ff, 4096, 4096, 4096, 1024, Z0,Z0,Z0,Z0,Z0,Z0, 1, 1.f);

    add_subnorm<<<BB * TT, 256>>>(ff, o2, out);
}

// round 5
// speedup vs baseline: 1.5027x; 1.5027x over previous
#include <cuda_runtime.h>
#include <math.h>
#include <stdint.h>

#define BB 4
#define TT 1024
#define DD 1024
#define HH 16
#define DKV 64
#define FFD 4096

// ---------------- scratch (device globals; no allocation allowed) ----------------
__device__ float g_Wt0[DD * DD];
__device__ float g_Wt1[DD * DD];
__device__ float g_Wt2[DD * DD];
__device__ float g_WoT[DD * DD];
__device__ float g_Q  [BB * TT * DD];
__device__ float g_K  [BB * TT * DD];
__device__ float g_V  [BB * TT * DD];
__device__ float g_Vt [BB * HH * DKV * TT];
__device__ float g_S  [(size_t)BB * HH * TT * TT];   // 256 MB
__device__ float g_dinv[BB * HH * TT];
__device__ float g_P  [BB * TT * DD];
__device__ float g_M  [BB * TT * DD];
__device__ float g_o1 [BB * TT * DD];
__device__ float g_o2 [BB * TT * DD];
__device__ float g_hid[(size_t)BB * TT * FFD];       // 64 MB
__device__ float g_ff [BB * TT * DD];

// ---------------- helpers ----------------
__device__ __forceinline__ uint32_t smem_u32(const void* p) {
    uint32_t a;
    asm("{ .reg .u64 t; cvta.to.shared.u64 t, %1; cvt.u32.u64 %0, t; }" : "=r"(a) : "l"(p));
    return a;
}
// pack bf16(trunc) of two floats: {hi16(b) : hi16(a)} -> (a low half = smaller k)
__device__ __forceinline__ uint32_t pack_bf16(float a, float b) {
    uint32_t d;
    asm("prmt.b32 %0, %1, %2, 0x7632;" : "=r"(d)
        : "r"(__float_as_uint(a)), "r"(__float_as_uint(b)));
    return d;
}
// exact residual after bf16 truncation
__device__ __forceinline__ float resid(float v) {
    return v - __uint_as_float(__float_as_uint(v) & 0xffff0000u);
}
__device__ __forceinline__ void mma_bf16(float* c, const uint32_t* a, const uint32_t* b) {
    asm volatile(
        "mma.sync.aligned.m16n8k16.row.col.f32.bf16.bf16.f32 "
        "{%0,%1,%2,%3}, {%4,%5,%6,%7}, {%8,%9}, {%0,%1,%2,%3};"
        : "+f"(c[0]), "+f"(c[1]), "+f"(c[2]), "+f"(c[3])
        : "r"(a[0]), "r"(a[1]), "r"(a[2]), "r"(a[3]), "r"(b[0]), "r"(b[1]));
}

// ---------------- bf16x3 mma GEMM: C[M,N] = alpha * A[M,K] @ B[N,K]^T -------------
// A K-major (lda), B K-major (ldb). 3-term bf16 split (hi*hi + hi*lo + lo*hi).
// BM=128, BN=64, BK=32, 2-stage cp.async, persistent CTAs over all tiles.
// k columns inside each 16-wide MMA chunk are logically permuted (identically
// for A and B) so each thread's fragment k-quad is one float4 in shared memory.
template<bool BIAS_, bool RELU_, bool EXP_>
__global__ __launch_bounds__(256, 3)
void mma_gemm(const float* __restrict__ A, const float* __restrict__ B,
              const float* __restrict__ bias, float* __restrict__ C,
              int K, int lda, int ldb, int ldc,
              long sA1, long sA2, long sB1, long sB2, long sC1, long sC2,
              int zdiv, float alpha, int gx, int gy, int ntiles)
{
    constexpr int BM = 128, BN = 64, BK = 32;
    constexpr int WN = BN / 2;         // 32 (warps: 4 x 2)
    constexpr int NT = WN / 8;         // 4
    constexpr int MT = 2;              // 32 rows per warp
    constexpr int RS = 48;             // smem row stride floats: 16r+4c mod 32 distinct
    constexpr int STG = (BM + BN) * RS;
    constexpr int NLD = (BM + BN) * 8; // float4 loads per stage

    extern __shared__ float sm[];
    const uint32_t smb = smem_u32(sm);

    const int tid  = threadIdx.x;
    const int lane = tid & 31;
    const int wid  = tid >> 5;
    const int wm   = wid >> 1;
    const int wn   = wid & 1;
    const int g    = lane >> 2;        // fragment row/col group
    const int tg   = lane & 3;         // k quad selector

    const int ar = wm * 32 + g;
    const int br = wn * WN + g;

    for (int tile = blockIdx.x; tile < ntiles; tile += gridDim.x) {
        const int z   = tile / (gx * gy);
        const int rem = tile % (gx * gy);
        const int row0 = (rem / gx) * BM;
        const int col0 = (rem % gx) * BN;
        const int z1 = z / zdiv, z2 = z % zdiv;
        const float* At = A + z1 * sA1 + z2 * sA2;
        const float* Bt = B + z1 * sB1 + z2 * sB2;
        float*       Ct = C + z1 * sC1 + z2 * sC2;

        float acc[MT][NT][4];
        #pragma unroll
        for (int i = 0; i < MT; i++)
            #pragma unroll
            for (int j = 0; j < NT; j++)
                #pragma unroll
                for (int q = 0; q < 4; q++) acc[i][j][q] = 0.f;

        const int nch = K / BK;

        auto copy_stage = [&](int s, int c) {
            const int kk = c * BK;
            #pragma unroll
            for (int i = tid; i < NLD; i += 256) {
                const bool isA = (i < BM * 8);
                const int j = isA ? i : (i - BM * 8);
                const int r = j >> 3, c4 = j & 7;
                const float* gp = isA ? (At + (long)(row0 + r) * lda + kk + c4 * 4)
                                      : (Bt + (long)(col0 + r) * ldb + kk + c4 * 4);
                uint32_t dst = smb + 4u * (uint32_t)(s * STG + (isA ? 0 : BM * RS) + r * RS + c4 * 4);
                asm volatile("cp.async.cg.shared.global [%0], [%1], 16;" :: "r"(dst), "l"(gp));
            }
        };

        copy_stage(0, 0);
        asm volatile("cp.async.commit_group;" ::: "memory");

        for (int c = 0; c < nch; c++) {
            if (c + 1 < nch) copy_stage((c + 1) & 1, c + 1);
            asm volatile("cp.async.commit_group;" ::: "memory");
            asm volatile("cp.async.wait_group 1;" ::: "memory");
            __syncthreads();

            const float* As = sm + (c & 1) * STG;
            const float* Bs = As + BM * RS;

            #pragma unroll
            for (int ks = 0; ks < 2; ks++) {
                // A fragments: rows (ar, ar+8), k-quad at permuted cols ks*16 + tg*4
                uint32_t Ah[MT][4], Al[MT][4];
                #pragma unroll
                for (int mt = 0; mt < MT; mt++) {
                    const float* ap = As + (ar + mt * 16) * RS + ks * 16 + tg * 4;
                    float4 x0 = *(const float4*)ap;
                    float4 x1 = *(const float4*)(ap + 8 * RS);
                    Ah[mt][0] = pack_bf16(x0.x, x0.y);
                    Ah[mt][2] = pack_bf16(x0.z, x0.w);
                    Ah[mt][1] = pack_bf16(x1.x, x1.y);
                    Ah[mt][3] = pack_bf16(x1.z, x1.w);
                    Al[mt][0] = pack_bf16(resid(x0.x), resid(x0.y));
                    Al[mt][2] = pack_bf16(resid(x0.z), resid(x0.w));
                    Al[mt][1] = pack_bf16(resid(x1.x), resid(x1.y));
                    Al[mt][3] = pack_bf16(resid(x1.z), resid(x1.w));
                }
                #pragma unroll
                for (int nt = 0; nt < NT; nt++) {
                    float4 b = *(const float4*)(Bs + (br + nt * 8) * RS + ks * 16 + tg * 4);
                    uint32_t Bh[2], Bl[2];
                    Bh[0] = pack_bf16(b.x, b.y);
                    Bh[1] = pack_bf16(b.z, b.w);
                    Bl[0] = pack_bf16(resid(b.x), resid(b.y));
                    Bl[1] = pack_bf16(resid(b.z), resid(b.w));
                    #pragma unroll
                    for (int mt = 0; mt < MT; mt++) {
                        mma_bf16(acc[mt][nt], Ah[mt], Bh);
                        mma_bf16(acc[mt][nt], Ah[mt], Bl);
                        mma_bf16(acc[mt][nt], Al[mt], Bh);
                    }
                }
            }
            __syncthreads();
        }

        // epilogue
        const int rbase = row0 + wm * 32 + g;
        const int cbase = col0 + wn * WN + tg * 2;
        #pragma unroll
        for (int mt = 0; mt < MT; mt++) {
            #pragma unroll
            for (int half = 0; half < 2; half++) {
                const long gm = rbase + mt * 16 + half * 8;
                float* crow = Ct + gm * ldc;
                #pragma unroll
                for (int nt = 0; nt < NT; nt++) {
                    const int gn = cbase + nt * 8;
                    float v0 = acc[mt][nt][half * 2 + 0] * alpha;
                    float v1 = acc[mt][nt][half * 2 + 1] * alpha;
                    if (EXP_)  { v0 = __expf(v0); v1 = __expf(v1); }
                    if (BIAS_) { v0 += bias[gn]; v1 += bias[gn + 1]; }
                    if (RELU_) { v0 = fmaxf(v0, 0.f); v1 = fmaxf(v1, 0.f); }
                    float2 o; o.x = v0; o.y = v1;
                    *(float2*)(crow + gn) = o;
                }
            }
        }
    }
}

// ---------------- tiled transpose: out[z][c][r] = in[z][r][c] (* scale[z][r]) -----
template<bool SC>
__global__ void transpose_k(const float* __restrict__ in, float* __restrict__ out,
                            const float* __restrict__ scale,
                            int R, int C, int ldin, int ldout,
                            long inS1, long inS2, int zdiv)
{
    __shared__ float tile[32][33];
    const int z = blockIdx.z;
    in  += (long)(z / zdiv) * inS1 + (long)(z % zdiv) * inS2;
    out += (long)z * (long)C * ldout;
    if (SC) scale += (long)z * R;
    const int c0 = blockIdx.x * 32, r0 = blockIdx.y * 32;
    const int tx = threadIdx.x, ty = threadIdx.y;
    #pragma unroll
    for (int i = ty; i < 32; i += 8) {
        float v = in[(long)(r0 + i) * ldin + c0 + tx];
        if (SC) v *= scale[r0 + i];
        tile[i][tx] = v;
    }
    __syncthreads();
    #pragma unroll
    for (int i = ty; i < 32; i += 8)
        out[(long)(c0 + i) * ldout + r0 + tx] = tile[tx][i];
}

// -------- deterministic per-column (query-axis) softmax denominator --------------
__global__ void colsum_inv(const float* __restrict__ S, float* __restrict__ dinv) {
    const int z = blockIdx.y;
    const int s = blockIdx.x * 256 + threadIdx.x;
    const float* p = S + (long)z * 1048576 + s;
    float acc = 0.f;
    #pragma unroll 8
    for (int t = 0; t < 1024; t++) acc += p[(long)t * 1024];
    dinv[z * 1024 + s] = 1.f / acc;
}

// ---------------- reductions + sub_norm -------------------------------------------
__device__ __forceinline__ float blockReduceSum(float v) {
    __shared__ float sh[32];
    __syncthreads();
    int lane = threadIdx.x & 31, wid = threadIdx.x >> 5;
    #pragma unroll
    for (int o = 16; o; o >>= 1) v += __shfl_xor_sync(0xffffffffu, v, o);
    if (lane == 0) sh[wid] = v;
    __syncthreads();
    if (wid == 0) {
        v = (threadIdx.x < (blockDim.x >> 5)) ? sh[lane] : 0.f;
        #pragma unroll
        for (int o = 16; o; o >>= 1) v += __shfl_xor_sync(0xffffffffu, v, o);
        if (lane == 0) sh[0] = v;
    }
    __syncthreads();
    return sh[0];
}

__global__ void add_subnorm(const float* __restrict__ A, const float* __restrict__ R,
                            float* __restrict__ O) {
    long base = (long)blockIdx.x * 1024;
    int t = threadIdx.x;
    float v[4];
    float s = 0.f;
    #pragma unroll
    for (int j = 0; j < 4; j++) { v[j] = A[base + t + j * 256] + R[base + t + j * 256]; s += v[j]; }
    s = blockReduceSum(s);
    float mean = s * (1.f / 1024.f);
    float q = 0.f;
    #pragma unroll
    for (int j = 0; j < 4; j++) { float d = v[j] - mean; q += d * d; }
    q = blockReduceSum(q);
    float sd = sqrtf(q * (1.f / 1023.f));
    #pragma unroll
    for (int j = 0; j < 4; j++) O[base + t + j * 256] = v[j] - mean - sd;
}

// ---------------- host --------------------------------------------------------------
static const int SMB   = 2 * (128 + 64) * 48 * 4;  // 73,728 B -> 3 CTAs/SM
static const int PGRID = 456;                      // 152 SMs x 3 CTAs

extern "C" void kernel_launch(void* const* d_in, const int* in_sizes, int n_in,
                              void* d_out, int out_size) {
    const float* x    = (const float*)d_in[0];
    const float* y    = (const float*)d_in[1];
    const float* Wq1  = (const float*)d_in[2];
    const float* Wk1  = (const float*)d_in[3];
    const float* Wv1  = (const float*)d_in[4];
    const float* Wo1  = (const float*)d_in[5];
    const float* Wq2  = (const float*)d_in[6];
    const float* Wk2  = (const float*)d_in[7];
    const float* Wv2  = (const float*)d_in[8];
    const float* Wo2  = (const float*)d_in[9];
    const float* W_in = (const float*)d_in[10];
    const float* b_in = (const float*)d_in[11];
    const float* W_out= (const float*)d_in[12];
    const float* b_out= (const float*)d_in[13];
    float* out = (float*)d_out;

    float *Wt0, *Wt1, *Wt2, *WoT, *Q, *K, *V, *Vt, *S, *dinv, *P, *M, *o1, *o2, *hid, *ff;
    cudaGetSymbolAddress((void**)&Wt0, g_Wt0);
    cudaGetSymbolAddress((void**)&Wt1, g_Wt1);
    cudaGetSymbolAddress((void**)&Wt2, g_Wt2);
    cudaGetSymbolAddress((void**)&WoT, g_WoT);
    cudaGetSymbolAddress((void**)&Q,   g_Q);
    cudaGetSymbolAddress((void**)&K,   g_K);
    cudaGetSymbolAddress((void**)&V,   g_V);
    cudaGetSymbolAddress((void**)&Vt,  g_Vt);
    cudaGetSymbolAddress((void**)&S,   g_S);
    cudaGetSymbolAddress((void**)&dinv,g_dinv);
    cudaGetSymbolAddress((void**)&P,   g_P);
    cudaGetSymbolAddress((void**)&M,   g_M);
    cudaGetSymbolAddress((void**)&o1,  g_o1);
    cudaGetSymbolAddress((void**)&o2,  g_o2);
    cudaGetSymbolAddress((void**)&hid, g_hid);
    cudaGetSymbolAddress((void**)&ff,  g_ff);

    cudaFuncSetAttribute(mma_gemm<false,false,false>, cudaFuncAttributeMaxDynamicSharedMemorySize, SMB);
    cudaFuncSetAttribute(mma_gemm<false,false,true >, cudaFuncAttributeMaxDynamicSharedMemorySize, SMB);
    cudaFuncSetAttribute(mma_gemm<true ,true ,false>, cudaFuncAttributeMaxDynamicSharedMemorySize, SMB);
    cudaFuncSetAttribute(mma_gemm<true ,false,false>, cudaFuncAttributeMaxDynamicSharedMemorySize, SMB);

    dim3 blkT(32, 8);
    const long Z0 = 0;

    auto glaunch = [&](int gx, int gy, int gz) {
        int nt = gx * gy * gz;
        return dim3((unsigned)(nt < PGRID ? nt : PGRID), 1, 1);
    };

    auto run_mha = [&](const float* qsrc, const float* kvsrc,
                       const float* Wq, const float* Wk, const float* Wv, const float* Wo,
                       const float* resid, float* obuf) {
        // repack per-head weights (H,D,dk) -> [(h,k), d]
        dim3 gw(2, 32, HH);
        transpose_k<false><<<gw, blkT>>>(Wq, Wt0, nullptr, 1024, 64, 64, 1024, 65536, 0, 1);
        transpose_k<false><<<gw, blkT>>>(Wk, Wt1, nullptr, 1024, 64, 64, 1024, 65536, 0, 1);
        transpose_k<false><<<gw, blkT>>>(Wv, Wt2, nullptr, 1024, 64, 64, 1024, 65536, 0, 1);

        // projections: (4096,1024) x (1024,1024)^T   tiles: 16 x 32 x 1
        mma_gemm<false,false,false><<<glaunch(16,32,1), 256, SMB>>>(
            qsrc, Wt0, nullptr, Q, 1024, 1024, 1024, 1024,
            Z0,Z0,Z0,Z0,Z0,Z0, 1, 1.f, 16, 32, 512);
        mma_gemm<false,false,false><<<glaunch(16,32,1), 256, SMB>>>(
            kvsrc, Wt1, nullptr, K, 1024, 1024, 1024, 1024,
            Z0,Z0,Z0,Z0,Z0,Z0, 1, 1.f, 16, 32, 512);
        mma_gemm<false,false,false><<<glaunch(16,32,1), 256, SMB>>>(
            kvsrc, Wt2, nullptr, V, 1024, 1024, 1024, 1024,
            Z0,Z0,Z0,Z0,Z0,Z0, 1, 1.f, 16, 32, 512);

        // scores: S[(b,h), t, s] = exp( Q.K^T / 8 )   tiles: 16 x 8 x 64
        mma_gemm<false,false,true><<<glaunch(16,8,64), 256, SMB>>>(
            Q, K, nullptr, S, 64, 1024, 1024, 1024,
            1048576, 64, 1048576, 64, 16777216, 1048576, HH, 0.125f, 16, 8, 8192);

        // softmax denominator over query axis t (deterministic column sums)
        colsum_inv<<<dim3(4, BB * HH), 256>>>(S, dinv);

        // V transpose + fold dinv: Vt[(b,h), v, s] = V[b, s, (h,v)] * dinv[(b,h), s]
        dim3 gv(2, 32, BB * HH);
        transpose_k<true><<<gv, blkT>>>(V, Vt, dinv, 1024, 64, 1024, 1024, 1048576, 64, HH);

        // partial: P[b, t, (h,v)] = sum_s expS[t,s] * Vt'[v,s]   tiles: 1 x 8 x 64
        mma_gemm<false,false,false><<<glaunch(1,8,64), 256, SMB>>>(
            S, Vt, nullptr, P, 1024, 1024, 1024, 1024,
            16777216, 1048576, 1048576, 65536, 1048576, 64, HH, 1.f, 1, 8, 512);

        // output projection
        dim3 gwo(32, 32, 1);
        transpose_k<false><<<gwo, blkT>>>(Wo, WoT, nullptr, 1024, 1024, 1024, 1024, Z0, Z0, 1);
        mma_gemm<false,false,false><<<glaunch(16,32,1), 256, SMB>>>(
            P, WoT, nullptr, M, 1024, 1024, 1024, 1024,
            Z0,Z0,Z0,Z0,Z0,Z0, 1, 1.f, 16, 32, 512);

        add_subnorm<<<BB * TT, 256>>>(M, resid, obuf);
    };

    // out1 = sub_norm(mha(y,y,y) + y)
    run_mha(y, y, Wq1, Wk1, Wv1, Wo1, y, o1);
    // out2 = sub_norm(mha(y,x,x) + out1)
    run_mha(y, x, Wq2, Wk2, Wv2, Wo2, o1, o2);

    // FFN on y: hid = relu(y @ W_in^T + b_in)   tiles: 64 x 32
    mma_gemm<true,true,false><<<glaunch(64,32,1), 256, SMB>>>(
        y, W_in, b_in, hid, 1024, 1024, 1024, 4096,
        Z0,Z0,Z0,Z0,Z0,Z0, 1, 1.f, 64, 32, 2048);
    // ff = hid @ W_out^T + b_out   tiles: 16 x 32
    mma_gemm<true,false,false><<<glaunch(16,32,1), 256, SMB>>>(
        hid, W_out, b_out, ff, 4096, 4096, 4096, 1024,
        Z0,Z0,Z0,Z0,Z0,Z0, 1, 1.f, 16, 32, 512);

    add_subnorm<<<BB * TT, 256>>>(ff, o2, out);
}